// round 7
// baseline (speedup 1.0000x reference)
#include <cuda_runtime.h>
#include <cstdint>

#define BB 2
#define SS 4096
#define HH 512
#define NH 8
#define HD 64
#define MROWS (BB * SS)
#define QKV_COLS (3 * HH)
#define LOG2D (-0.15200309344504997f)   // log2(0.9)
#define QSCALE 0.18033688011112042f     // 0.125 * log2(e)

__device__ float g_qkv[MROWS * QKV_COLS];
__device__ float g_vT[BB * NH * HD * SS];
__device__ float g_attn[MROWS * HH];

__device__ __forceinline__ uint32_t f2tf(float x) {
    uint32_t r;
    asm("cvt.rna.tf32.f32 %0, %1;" : "=r"(r) : "f"(x));
    return r;
}
__device__ __forceinline__ float ex2(float x) {
    float r;
    asm("ex2.approx.ftz.f32 %0, %1;" : "=f"(r) : "f"(x));
    return r;
}
__device__ __forceinline__ void mma8(float* d, const uint32_t* a, const uint32_t* b) {
    asm volatile(
        "mma.sync.aligned.m16n8k8.row.col.f32.tf32.tf32.f32 "
        "{%0,%1,%2,%3}, {%4,%5,%6,%7}, {%8,%9}, {%0,%1,%2,%3};\n"
        : "+f"(d[0]), "+f"(d[1]), "+f"(d[2]), "+f"(d[3])
        : "r"(a[0]), "r"(a[1]), "r"(a[2]), "r"(a[3]), "r"(b[0]), "r"(b[1]));
}
__device__ __forceinline__ void ldsm4(uint32_t* r, uint32_t saddr) {
    asm volatile("ldmatrix.sync.aligned.m8n8.x4.shared.b16 {%0,%1,%2,%3}, [%4];"
                 : "=r"(r[0]), "=r"(r[1]), "=r"(r[2]), "=r"(r[3]) : "r"(saddr));
}
__device__ __forceinline__ void cpa16(uint32_t dst, const void* src) {
    asm volatile("cp.async.cg.shared.global [%0], [%1], 16;" :: "r"(dst), "l"(src));
}
#define CP_COMMIT() asm volatile("cp.async.commit_group;" ::: "memory")
#define CP_WAIT0()  asm volatile("cp.async.wait_group 0;" ::: "memory")

// fragment-offset helpers (byte offsets), stride S in words
#define AOFF(S) (((((mat & 1) << 3) + mr) * (S) + ((mat >> 1) << 2)) << 2)
#define BOFF(S) (((((mat >> 1) << 3) + mr) * (S) + ((mat & 1) << 2)) << 2)

// ---------------------------------------------------------------------------
// TF32 GEMM with ldmatrix fragments. CTA 128x64, 4 warps, K chunks of 32.
// Register-prefetched global loads (LDG of chunk k+1 before MMA of chunk k).
// mode 0: plain fp32 (+bias). mode 1: qkv epilogue (scale/round/V-scatter).
// ---------------------------------------------------------------------------
#define GSTR 36

__global__ __launch_bounds__(128, 2) void gemm_tc(
    const float* __restrict__ A, const float* __restrict__ W,
    const float* __restrict__ bias, float* __restrict__ C,
    float* __restrict__ vT, int Ndim, int Kdim, int mode)
{
    __shared__ uint32_t sA[128 * GSTR];
    __shared__ uint32_t sW[64 * GSTR];

    const int tid = threadIdx.x;
    const int w = tid >> 5, lane = tid & 31;
    const int g = lane >> 2, tg = lane & 3;
    const int mat = lane >> 3, mr = lane & 7;
    const int m0 = blockIdx.y * 128;
    const int n0 = blockIdx.x * 64;

    const uint32_t sAu = (uint32_t)__cvta_generic_to_shared(sA);
    const uint32_t sWu = (uint32_t)__cvta_generic_to_shared(sW);
    const uint32_t a_off = AOFF(GSTR);
    const uint32_t b_off = BOFF(GSTR);

    float acc[2][8][4] = {};
    float4 av[8], wv[4];

#pragma unroll
    for (int it = 0; it < 8; it++) {
        int fi = it * 128 + tid;
        int r = fi >> 3, c = (fi & 7) << 2;
        av[it] = *(const float4*)(A + (size_t)(m0 + r) * Kdim + c);
    }
#pragma unroll
    for (int it = 0; it < 4; it++) {
        int fi = it * 128 + tid;
        int r = fi >> 3, c = (fi & 7) << 2;
        wv[it] = *(const float4*)(W + (size_t)(n0 + r) * Kdim + c);
    }

    for (int kk = 0; kk < Kdim; kk += 32) {
        __syncthreads();
#pragma unroll
        for (int it = 0; it < 8; it++) {
            int fi = it * 128 + tid;
            int r = fi >> 3, c = (fi & 7) << 2;
            uint32_t* p = &sA[r * GSTR + c];
            p[0] = f2tf(av[it].x); p[1] = f2tf(av[it].y);
            p[2] = f2tf(av[it].z); p[3] = f2tf(av[it].w);
        }
#pragma unroll
        for (int it = 0; it < 4; it++) {
            int fi = it * 128 + tid;
            int r = fi >> 3, c = (fi & 7) << 2;
            uint32_t* p = &sW[r * GSTR + c];
            p[0] = f2tf(wv[it].x); p[1] = f2tf(wv[it].y);
            p[2] = f2tf(wv[it].z); p[3] = f2tf(wv[it].w);
        }
        __syncthreads();
        if (kk + 32 < Kdim) {
#pragma unroll
            for (int it = 0; it < 8; it++) {
                int fi = it * 128 + tid;
                int r = fi >> 3, c = (fi & 7) << 2;
                av[it] = *(const float4*)(A + (size_t)(m0 + r) * Kdim + kk + 32 + c);
            }
#pragma unroll
            for (int it = 0; it < 4; it++) {
                int fi = it * 128 + tid;
                int r = fi >> 3, c = (fi & 7) << 2;
                wv[it] = *(const float4*)(W + (size_t)(n0 + r) * Kdim + kk + 32 + c);
            }
        }
#pragma unroll
        for (int ks = 0; ks < 4; ks++) {
            uint32_t afr[2][4];
            ldsm4(afr[0], sAu + (w * 32) * (GSTR * 4) + a_off + ks * 32);
            ldsm4(afr[1], sAu + (w * 32 + 16) * (GSTR * 4) + a_off + ks * 32);
#pragma unroll
            for (int p = 0; p < 4; p++) {
                uint32_t bfr[4];
                ldsm4(bfr, sWu + p * 16 * (GSTR * 4) + b_off + ks * 32);
                mma8(acc[0][2 * p + 0], afr[0], bfr);
                mma8(acc[0][2 * p + 1], afr[0], bfr + 2);
                mma8(acc[1][2 * p + 0], afr[1], bfr);
                mma8(acc[1][2 * p + 1], afr[1], bfr + 2);
            }
        }
    }

#pragma unroll
    for (int mi = 0; mi < 2; mi++)
#pragma unroll
        for (int ni = 0; ni < 8; ni++) {
            float* a = acc[mi][ni];
            int row = m0 + w * 32 + mi * 16 + g;
            int col = n0 + ni * 8 + tg * 2;
            if (mode == 0) {
                float b0 = bias ? bias[col] : 0.f;
                float b1 = bias ? bias[col + 1] : 0.f;
                *(float2*)(C + (size_t)row * Ndim + col) = make_float2(a[0] + b0, a[1] + b1);
                *(float2*)(C + (size_t)(row + 8) * Ndim + col) = make_float2(a[2] + b0, a[3] + b1);
            } else {
                int region = n0 >> 9;
                if (region < 2) {
                    float scl = (region == 0) ? QSCALE : 1.f;
                    *(float2*)(C + (size_t)row * Ndim + col) =
                        make_float2(__uint_as_float(f2tf(a[0] * scl)),
                                    __uint_as_float(f2tf(a[1] * scl)));
                    *(float2*)(C + (size_t)(row + 8) * Ndim + col) =
                        make_float2(__uint_as_float(f2tf(a[2] * scl)),
                                    __uint_as_float(f2tf(a[3] * scl)));
                } else {
                    int b = row >> 12, s = row & 4095;
                    int hv = (col - 1024) >> 6, d = (col - 1024) & 63;
                    float* vb = vT + (size_t)((b * NH + hv) * HD) * SS;
                    vb[(size_t)d * SS + s]           = __uint_as_float(f2tf(a[0]));
                    vb[(size_t)(d + 1) * SS + s]     = __uint_as_float(f2tf(a[1]));
                    vb[(size_t)d * SS + s + 8]       = __uint_as_float(f2tf(a[2]));
                    vb[(size_t)(d + 1) * SS + s + 8] = __uint_as_float(f2tf(a[3]));
                }
            }
        }
}

// ---------------------------------------------------------------------------
// TF32 flash attention with ANALYTIC-SHIFT softmax:
//   exponent = s + min(k,q)*log2(0.9)   (exact row-max shift of the bias term;
//   retained exponents bounded above by |s| ~ 10, underflow-to-0 correct).
// 256 threads / 8 warps, 128 q per CTA, K-tiles of 32, double-buffered K/V.
// Q/K pre-rounded tf32 (Q pre-scaled by 0.125*log2e), V pre-transposed [d][s].
// ---------------------------------------------------------------------------
#define QS 68
#define KSs 68
#define VS 36
#define PS 36
#define W_K0 (128 * QS)
#define W_V0 (W_K0 + 2 * 32 * KSs)
#define W_P  (W_V0 + 2 * 64 * VS)
#define ATTN_SMEM ((W_P + 128 * PS) * 4)   // 89088 bytes -> 2 CTAs/SM

__global__ __launch_bounds__(256, 2) void attn_tc(
    const float* __restrict__ qkv, const float* __restrict__ vT,
    float* __restrict__ out)
{
    extern __shared__ uint32_t sm[];

    const int tid = threadIdx.x;
    const int w = tid >> 5, lane = tid & 31;
    const int g = lane >> 2, tg = lane & 3;
    const int mat = lane >> 3, mr = lane & 7;
    const int q0 = blockIdx.x * 128;
    const int bh = blockIdx.y;
    const int b = bh >> 3, h = bh & 7;

    const float* qbase = qkv + (size_t)b * SS * QKV_COLS + h * HD;
    const float* kbase = qbase + HH;
    const float* vtb = vT + (size_t)bh * HD * SS;

    const uint32_t smu = (uint32_t)__cvta_generic_to_shared(sm);
    const uint32_t sQu = smu;
    const uint32_t sKu[2] = {smu + W_K0 * 4, smu + (W_K0 + 32 * KSs) * 4};
    const uint32_t sVu[2] = {smu + W_V0 * 4, smu + (W_V0 + 64 * VS) * 4};
    const uint32_t sPu = smu + W_P * 4;

    const uint32_t qa = sQu + w * (16 * QS * 4) + AOFF(QS);
    const uint32_t pa = sPu + w * (16 * PS * 4) + AOFF(PS);
    const uint32_t boffK = BOFF(KSs);
    const uint32_t boffV = BOFF(VS);

    // prologue: Q (128x64) + K/V tile 0
    {
#pragma unroll
        for (int it = 0; it < 8; it++) {
            int fi = it * 256 + tid;
            int r = fi >> 4, c = (fi & 15) << 2;
            cpa16(sQu + (r * QS + c) * 4, qbase + (size_t)(q0 + r) * QKV_COLS + c);
        }
#pragma unroll
        for (int it = 0; it < 2; it++) {
            int fi = it * 256 + tid;
            int r = fi >> 4, c = (fi & 15) << 2;
            cpa16(sKu[0] + (r * KSs + c) * 4, kbase + (size_t)r * QKV_COLS + c);
        }
#pragma unroll
        for (int it = 0; it < 2; it++) {
            int fi = it * 256 + tid;
            int r = fi >> 3, c = (fi & 7) << 2;
            cpa16(sVu[0] + (r * VS + c) * 4, vtb + (size_t)r * SS + c);
        }
        CP_COMMIT();
    }

    float oc[8][4] = {};
    float lacc[2] = {0.f, 0.f};

    for (int t = 0; t < SS / 32; t++) {
        const int kt = t * 32;
        const int cur = t & 1, nxt = cur ^ 1;

        CP_WAIT0();
        __syncthreads();

        if (t + 1 < SS / 32) {
#pragma unroll
            for (int it = 0; it < 2; it++) {
                int fi = it * 256 + tid;
                int r = fi >> 4, c = (fi & 15) << 2;
                cpa16(sKu[nxt] + (r * KSs + c) * 4,
                      kbase + (size_t)(kt + 32 + r) * QKV_COLS + c);
            }
#pragma unroll
            for (int it = 0; it < 2; it++) {
                int fi = it * 256 + tid;
                int r = fi >> 3, c = (fi & 7) << 2;
                cpa16(sVu[nxt] + (r * VS + c) * 4,
                      vtb + (size_t)r * SS + kt + 32 + c);
            }
            CP_COMMIT();
        }

        // S = Q K^T
        float sc[4][4] = {};
#pragma unroll
        for (int ks = 0; ks < 8; ks++) {
            uint32_t afr[4];
            ldsm4(afr, qa + ks * 32);
#pragma unroll
            for (int p = 0; p < 2; p++) {
                uint32_t bfr[4];
                ldsm4(bfr, sKu[cur] + boffK + p * (16 * KSs * 4) + ks * 32);
                mma8(sc[2 * p + 0], afr, bfr);
                mma8(sc[2 * p + 1], afr, bfr + 2);
            }
        }

        // analytic-shift softmax: e = exp2(s + min(k,q)*log2(0.9))
#pragma unroll
        for (int hi = 0; hi < 2; hi++) {
            int qg = q0 + w * 16 + hi * 8 + g;
            int prow = w * 16 + hi * 8 + g;
#pragma unroll
            for (int ni = 0; ni < 4; ni++) {
                uint32_t eb[2];
#pragma unroll
                for (int cc = 0; cc < 2; cc++) {
                    int kg = kt + ni * 8 + tg * 2 + cc;
                    float mk = (float)min(kg, qg);
                    float e = ex2(fmaf(mk, LOG2D, sc[ni][hi * 2 + cc]));
                    eb[cc] = f2tf(e);
                    lacc[hi] += __uint_as_float(eb[cc]);
                }
                uint32_t addr = sPu + (prow * PS + ni * 8 + tg * 2) * 4;
                asm volatile("st.shared.v2.u32 [%0], {%1,%2};"
                             :: "r"(addr), "r"(eb[0]), "r"(eb[1]));
            }
        }
        __syncwarp();   // P rows are warp-private

        // O += P V
#pragma unroll
        for (int ks = 0; ks < 4; ks++) {
            uint32_t pfr[4];
            ldsm4(pfr, pa + ks * 32);
#pragma unroll
            for (int p = 0; p < 4; p++) {
                uint32_t vfr[4];
                ldsm4(vfr, sVu[cur] + boffV + p * (16 * VS * 4) + ks * 32);
                mma8(oc[2 * p + 0], pfr, vfr);
                mma8(oc[2 * p + 1], pfr, vfr + 2);
            }
        }
    }

    float l0 = lacc[0], l1 = lacc[1];
    l0 += __shfl_xor_sync(0xffffffffu, l0, 1);
    l0 += __shfl_xor_sync(0xffffffffu, l0, 2);
    l1 += __shfl_xor_sync(0xffffffffu, l1, 1);
    l1 += __shfl_xor_sync(0xffffffffu, l1, 2);
    float inv0 = 1.0f / l0, inv1 = 1.0f / l1;
#pragma unroll
    for (int ni = 0; ni < 8; ni++) {
        int row = q0 + w * 16 + g;
        int col = h * HD + ni * 8 + tg * 2;
        *(float2*)(out + (size_t)(b * SS + row) * HH + col) =
            make_float2(oc[ni][0] * inv0, oc[ni][1] * inv0);
        *(float2*)(out + (size_t)(b * SS + row + 8) * HH + col) =
            make_float2(oc[ni][2] * inv1, oc[ni][3] * inv1);
    }
}

// ---------------------------------------------------------------------------
extern "C" void kernel_launch(void* const* d_in, const int* in_sizes, int n_in,
                              void* d_out, int out_size)
{
    (void)in_sizes; (void)n_in; (void)out_size;
    const float* x    = (const float*)d_in[0];
    const float* wqkv = (const float*)d_in[1];
    const float* wout = (const float*)d_in[2];
    const float* bout = (const float*)d_in[3];
    float* out = (float*)d_out;

    void *qkv_ptr = nullptr, *vT_ptr = nullptr, *attn_ptr = nullptr;
    cudaGetSymbolAddress(&qkv_ptr, g_qkv);
    cudaGetSymbolAddress(&vT_ptr, g_vT);
    cudaGetSymbolAddress(&attn_ptr, g_attn);

    cudaFuncSetAttribute(attn_tc, cudaFuncAttributeMaxDynamicSharedMemorySize, ATTN_SMEM);

    gemm_tc<<<dim3(QKV_COLS / 64, MROWS / 128), 128>>>(
        x, wqkv, nullptr, (float*)qkv_ptr, (float*)vT_ptr, QKV_COLS, HH, 1);
    attn_tc<<<dim3(SS / 128, BB * NH), 256, ATTN_SMEM>>>(
        (const float*)qkv_ptr, (const float*)vT_ptr, (float*)attn_ptr);
    gemm_tc<<<dim3(HH / 64, MROWS / 128), 128>>>(
        (const float*)attn_ptr, wout, bout, out, nullptr, HH, HH, 0);
}

// round 8
// speedup vs baseline: 2.6911x; 2.6911x over previous
#include <cuda_runtime.h>
#include <cstdint>

#define BB 2
#define SS 4096
#define HH 512
#define NH 8
#define HD 64
#define MROWS (BB * SS)
#define QKV_COLS (3 * HH)
#define LOG2D (-0.15200309344504997f)   // log2(0.9)
#define QSCALE 0.18033688011112042f     // 0.125 * log2(e)

// scratch (device globals; no allocation allowed)
__device__ float g_xr[MROWS * HH];            // x rounded to tf32
__device__ float g_wqkvr[QKV_COLS * HH];      // w_qkv rounded
__device__ float g_woutr[HH * HH];            // w_out rounded
__device__ float g_qkv[MROWS * QKV_COLS];     // Q|K regions (tf32-rounded)
__device__ float g_vT[BB * NH * HD * SS];     // V transposed [b][h][d][s]
__device__ float g_attn[MROWS * HH];          // attention out (tf32-rounded)
__device__ float g_pO[512 * 128 * 64];        // split-K partial O
__device__ float g_pl[512 * 128];             // split-K partial l

__device__ __forceinline__ uint32_t f2tf(float x) {
    uint32_t r;
    asm("cvt.rna.tf32.f32 %0, %1;" : "=r"(r) : "f"(x));
    return r;
}
__device__ __forceinline__ float rtf(float x) { return __uint_as_float(f2tf(x)); }
__device__ __forceinline__ float ex2(float x) {
    float r;
    asm("ex2.approx.ftz.f32 %0, %1;" : "=f"(r) : "f"(x));
    return r;
}
__device__ __forceinline__ void mma8(float* d, const uint32_t* a, const uint32_t* b) {
    asm volatile(
        "mma.sync.aligned.m16n8k8.row.col.f32.tf32.tf32.f32 "
        "{%0,%1,%2,%3}, {%4,%5,%6,%7}, {%8,%9}, {%0,%1,%2,%3};\n"
        : "+f"(d[0]), "+f"(d[1]), "+f"(d[2]), "+f"(d[3])
        : "r"(a[0]), "r"(a[1]), "r"(a[2]), "r"(a[3]), "r"(b[0]), "r"(b[1]));
}
__device__ __forceinline__ void ldsm4(uint32_t* r, uint32_t saddr) {
    asm volatile("ldmatrix.sync.aligned.m8n8.x4.shared.b16 {%0,%1,%2,%3}, [%4];"
                 : "=r"(r[0]), "=r"(r[1]), "=r"(r[2]), "=r"(r[3]) : "r"(saddr));
}
__device__ __forceinline__ void cpa16(uint32_t dst, const void* src) {
    asm volatile("cp.async.cg.shared.global [%0], [%1], 16;" :: "r"(dst), "l"(src));
}
#define CP_COMMIT() asm volatile("cp.async.commit_group;" ::: "memory")
#define CP_WAIT0()  asm volatile("cp.async.wait_group 0;" ::: "memory")

#define AOFF(S) (((((mat & 1) << 3) + mr) * (S) + ((mat >> 1) << 2)) << 2)
#define BOFF(S) (((((mat >> 1) << 3) + mr) * (S) + ((mat & 1) << 2)) << 2)

// ---------------------------------------------------------------------------
// tf32 pre-round pass (elementwise, float4)
// ---------------------------------------------------------------------------
__global__ void round_tf(const float* __restrict__ src, float* __restrict__ dst, int n4) {
    int i = blockIdx.x * 256 + threadIdx.x;
    if (i < n4) {
        float4 v = ((const float4*)src)[i];
        v.x = rtf(v.x); v.y = rtf(v.y); v.z = rtf(v.z); v.w = rtf(v.w);
        ((float4*)dst)[i] = v;
    }
}

// ---------------------------------------------------------------------------
// GEMM, inputs pre-rounded tf32. CTA 128x128, 8 warps (32m x 64n each),
// K chunks of 32, cp.async double-buffered, no conversions in mainloop.
// mode 0: fp32 +bias. mode 1: qkv epilogue (Q scale/round, K round, V scatter).
// ---------------------------------------------------------------------------
#define GSTR 36
#define GEMM_SMEM (4 * 128 * GSTR * 4)   // 73728 B (A+B, 2 buffers)

__global__ __launch_bounds__(256, 2) void gemm_db(
    const float* __restrict__ A, const float* __restrict__ W,
    const float* __restrict__ bias, float* __restrict__ C,
    float* __restrict__ vT, int Ndim, int Kdim, int mode)
{
    extern __shared__ uint32_t gsm[];
    const int tid = threadIdx.x;
    const int w = tid >> 5, lane = tid & 31;
    const int g = lane >> 2, tg = lane & 3;
    const int mat = lane >> 3, mr = lane & 7;
    const int wm = w & 3, wn = w >> 2;
    const int m0 = blockIdx.y * 128, n0 = blockIdx.x * 128;

    const uint32_t smu = (uint32_t)__cvta_generic_to_shared(gsm);
    const uint32_t sAu[2] = {smu, smu + 128 * GSTR * 4};
    const uint32_t sBu[2] = {smu + 2 * 128 * GSTR * 4, smu + 3 * 128 * GSTR * 4};
    const uint32_t a_off = AOFF(GSTR), b_off = BOFF(GSTR);

    float acc[2][8][4] = {};
    const int T = Kdim / 32;

    // issue chunk t into buffer buf
#define GISSUE(t_, buf_) {                                                     \
        int kk_ = (t_) * 32;                                                   \
        _Pragma("unroll")                                                      \
        for (int it = 0; it < 4; it++) {                                       \
            int fi = it * 256 + tid;                                           \
            int r = fi >> 3, c = (fi & 7) << 2;                                \
            cpa16(sAu[buf_] + (r * GSTR + c) * 4,                              \
                  A + (size_t)(m0 + r) * Kdim + kk_ + c);                      \
            cpa16(sBu[buf_] + (r * GSTR + c) * 4,                              \
                  W + (size_t)(n0 + r) * Kdim + kk_ + c);                      \
        }                                                                      \
        CP_COMMIT();                                                           \
    }

    GISSUE(0, 0);
    for (int t = 0; t < T; t++) {
        const int cur = t & 1;
        CP_WAIT0();
        __syncthreads();
        if (t + 1 < T) GISSUE(t + 1, cur ^ 1);
#pragma unroll
        for (int ks = 0; ks < 4; ks++) {
            uint32_t afr[2][4];
            ldsm4(afr[0], sAu[cur] + (wm * 32) * (GSTR * 4) + a_off + ks * 32);
            ldsm4(afr[1], sAu[cur] + (wm * 32 + 16) * (GSTR * 4) + a_off + ks * 32);
#pragma unroll
            for (int p = 0; p < 4; p++) {
                uint32_t bfr[4];
                ldsm4(bfr, sBu[cur] + (wn * 64 + p * 16) * (GSTR * 4) + b_off + ks * 32);
                mma8(acc[0][2 * p + 0], afr[0], bfr);
                mma8(acc[0][2 * p + 1], afr[0], bfr + 2);
                mma8(acc[1][2 * p + 0], afr[1], bfr);
                mma8(acc[1][2 * p + 1], afr[1], bfr + 2);
            }
        }
    }

#pragma unroll
    for (int mi = 0; mi < 2; mi++)
#pragma unroll
        for (int ni = 0; ni < 8; ni++) {
            float* a = acc[mi][ni];
            int row = m0 + wm * 32 + mi * 16 + g;
            int col = n0 + wn * 64 + ni * 8 + tg * 2;
            if (mode == 0) {
                float b0 = bias ? bias[col] : 0.f;
                float b1 = bias ? bias[col + 1] : 0.f;
                *(float2*)(C + (size_t)row * Ndim + col) = make_float2(a[0] + b0, a[1] + b1);
                *(float2*)(C + (size_t)(row + 8) * Ndim + col) = make_float2(a[2] + b0, a[3] + b1);
            } else {
                int region = n0 >> 9;   // 128-wide tiles never straddle 512 boundaries
                if (region < 2) {
                    float scl = (region == 0) ? QSCALE : 1.f;
                    *(float2*)(C + (size_t)row * Ndim + col) =
                        make_float2(rtf(a[0] * scl), rtf(a[1] * scl));
                    *(float2*)(C + (size_t)(row + 8) * Ndim + col) =
                        make_float2(rtf(a[2] * scl), rtf(a[3] * scl));
                } else {
                    int b = row >> 12, s = row & 4095;
                    int hv = (col - 1024) >> 6, d = (col - 1024) & 63;
                    float* vb = vT + (size_t)((b * NH + hv) * HD) * SS;
                    vb[(size_t)d * SS + s]           = rtf(a[0]);
                    vb[(size_t)(d + 1) * SS + s]     = rtf(a[1]);
                    vb[(size_t)d * SS + s + 8]       = rtf(a[2]);
                    vb[(size_t)(d + 1) * SS + s + 8] = rtf(a[3]);
                }
            }
        }
}

// ---------------------------------------------------------------------------
// TF32 flash attention with recency truncation + additive split-K.
// grid (60, 16): per head, CTA i<32 -> qtile i>>3 (<4), K-chunk i&7 (split);
// i>=32 -> qtile i-28 (>=4), K-chunk 0 only (keys [0,512): exact to ~2^-41).
// Every CTA: 128 q rows, 16 key-tiles of 32, double-buffered K/V.
// exponent = s + max(k,q-in-log2D-units) shift: e = ex2(s + fmax(kL, qL)).
// ---------------------------------------------------------------------------
#define QS 68
#define KSs 68
#define VS 36
#define PS 36
#define W_K0 (128 * QS)
#define W_V0 (W_K0 + 2 * 32 * KSs)
#define W_P  (W_V0 + 2 * 64 * VS)
#define ATTN_SMEM ((W_P + 128 * PS) * 4)   // 89088 B -> 2 CTAs/SM

__global__ __launch_bounds__(256, 2) void attn_tc(
    const float* __restrict__ qkv, const float* __restrict__ vT,
    float* __restrict__ out, float* __restrict__ pO, float* __restrict__ pl)
{
    extern __shared__ uint32_t sm[];

    const int tid = threadIdx.x;
    const int w = tid >> 5, lane = tid & 31;
    const int g = lane >> 2, tg = lane & 3;
    const int mat = lane >> 3, mr = lane & 7;
    const int bh = blockIdx.y;
    const int b = bh >> 3, h = bh & 7;

    int qt, ck;
    if (blockIdx.x < 32) { qt = blockIdx.x >> 3; ck = blockIdx.x & 7; }
    else                 { qt = blockIdx.x - 28; ck = 0; }
    const bool split = (blockIdx.x < 32);
    const int q0 = qt * 128;
    const int k0 = ck * 512;

    const float* qbase = qkv + (size_t)b * SS * QKV_COLS + h * HD;
    const float* kbase = qbase + HH;
    const float* vtb = vT + (size_t)bh * HD * SS;

    const uint32_t smu = (uint32_t)__cvta_generic_to_shared(sm);
    const uint32_t sQu = smu;
    const uint32_t sKu[2] = {smu + W_K0 * 4, smu + (W_K0 + 32 * KSs) * 4};
    const uint32_t sVu[2] = {smu + W_V0 * 4, smu + (W_V0 + 64 * VS) * 4};
    const uint32_t sPu = smu + W_P * 4;

    const uint32_t qa = sQu + w * (16 * QS * 4) + AOFF(QS);
    const uint32_t pa = sPu + w * (16 * PS * 4) + AOFF(PS);
    const uint32_t boffK = BOFF(KSs);
    const uint32_t boffV = BOFF(VS);

    // prologue: Q (128x64) + K/V tile 0
    {
#pragma unroll
        for (int it = 0; it < 8; it++) {
            int fi = it * 256 + tid;
            int r = fi >> 4, c = (fi & 15) << 2;
            cpa16(sQu + (r * QS + c) * 4, qbase + (size_t)(q0 + r) * QKV_COLS + c);
        }
#pragma unroll
        for (int it = 0; it < 2; it++) {
            int fi = it * 256 + tid;
            int r = fi >> 4, c = (fi & 15) << 2;
            cpa16(sKu[0] + (r * KSs + c) * 4, kbase + (size_t)(k0 + r) * QKV_COLS + c);
        }
#pragma unroll
        for (int it = 0; it < 2; it++) {
            int fi = it * 256 + tid;
            int r = fi >> 3, c = (fi & 7) << 2;
            cpa16(sVu[0] + (r * VS + c) * 4, vtb + (size_t)r * SS + k0 + c);
        }
        CP_COMMIT();
    }

    // per-thread column/row log2-decay constants
    float colL[4][2];
#pragma unroll
    for (int ni = 0; ni < 4; ni++)
#pragma unroll
        for (int cc = 0; cc < 2; cc++)
            colL[ni][cc] = (float)(k0 + ni * 8 + tg * 2 + cc) * LOG2D;
    float qLf[2];
#pragma unroll
    for (int hi = 0; hi < 2; hi++)
        qLf[hi] = (float)(q0 + w * 16 + hi * 8 + g) * LOG2D;

    float oc[8][4] = {};
    float lacc[2] = {0.f, 0.f};

    for (int t = 0; t < 16; t++) {
        const int kt = k0 + t * 32;
        const int cur = t & 1;

        CP_WAIT0();
        __syncthreads();

        if (t + 1 < 16) {
            const int nxt = cur ^ 1;
#pragma unroll
            for (int it = 0; it < 2; it++) {
                int fi = it * 256 + tid;
                int r = fi >> 4, c = (fi & 15) << 2;
                cpa16(sKu[nxt] + (r * KSs + c) * 4,
                      kbase + (size_t)(kt + 32 + r) * QKV_COLS + c);
            }
#pragma unroll
            for (int it = 0; it < 2; it++) {
                int fi = it * 256 + tid;
                int r = fi >> 3, c = (fi & 7) << 2;
                cpa16(sVu[nxt] + (r * VS + c) * 4,
                      vtb + (size_t)r * SS + kt + 32 + c);
            }
            CP_COMMIT();
        }

        // S = Q K^T
        float sc[4][4] = {};
#pragma unroll
        for (int ks = 0; ks < 8; ks++) {
            uint32_t afr[4];
            ldsm4(afr, qa + ks * 32);
#pragma unroll
            for (int p = 0; p < 2; p++) {
                uint32_t bfr[4];
                ldsm4(bfr, sKu[cur] + boffK + p * (16 * KSs * 4) + ks * 32);
                mma8(sc[2 * p + 0], afr, bfr);
                mma8(sc[2 * p + 1], afr, bfr + 2);
            }
        }

        // softmax: e = exp2(s + max(kL, qL))   (== s + min(k,q)*log2(0.9))
#pragma unroll
        for (int hi = 0; hi < 2; hi++) {
            int prow = w * 16 + hi * 8 + g;
#pragma unroll
            for (int ni = 0; ni < 4; ni++) {
                uint32_t eb[2];
#pragma unroll
                for (int cc = 0; cc < 2; cc++) {
                    float e = ex2(sc[ni][hi * 2 + cc] + fmaxf(colL[ni][cc], qLf[hi]));
                    eb[cc] = f2tf(e);
                    lacc[hi] += __uint_as_float(eb[cc]);
                }
                uint32_t addr = sPu + (prow * PS + ni * 8 + tg * 2) * 4;
                asm volatile("st.shared.v2.u32 [%0], {%1,%2};"
                             :: "r"(addr), "r"(eb[0]), "r"(eb[1]));
            }
        }
#pragma unroll
        for (int ni = 0; ni < 4; ni++) {
            colL[ni][0] += 32.f * LOG2D;
            colL[ni][1] += 32.f * LOG2D;
        }
        __syncwarp();

        // O += P V
#pragma unroll
        for (int ks = 0; ks < 4; ks++) {
            uint32_t pfr[4];
            ldsm4(pfr, pa + ks * 32);
#pragma unroll
            for (int p = 0; p < 4; p++) {
                uint32_t vfr[4];
                ldsm4(vfr, sVu[cur] + boffV + p * (16 * VS * 4) + ks * 32);
                mma8(oc[2 * p + 0], pfr, vfr);
                mma8(oc[2 * p + 1], pfr, vfr + 2);
            }
        }
    }

    float l0 = lacc[0], l1 = lacc[1];
    l0 += __shfl_xor_sync(0xffffffffu, l0, 1);
    l0 += __shfl_xor_sync(0xffffffffu, l0, 2);
    l1 += __shfl_xor_sync(0xffffffffu, l1, 1);
    l1 += __shfl_xor_sync(0xffffffffu, l1, 2);

    if (!split) {
        float inv0 = 1.0f / l0, inv1 = 1.0f / l1;
#pragma unroll
        for (int ni = 0; ni < 8; ni++) {
            int row = q0 + w * 16 + g;
            int col = h * HD + ni * 8 + tg * 2;
            *(float2*)(out + (size_t)(b * SS + row) * HH + col) =
                make_float2(rtf(oc[ni][0] * inv0), rtf(oc[ni][1] * inv0));
            *(float2*)(out + (size_t)(b * SS + row + 8) * HH + col) =
                make_float2(rtf(oc[ni][2] * inv1), rtf(oc[ni][3] * inv1));
        }
    } else {
        // additive split-K partials (analytic shift is chunk-invariant)
        int pi = (bh * 4 + qt) * 8 + ck;
        float* pOb = pO + (size_t)pi * (128 * 64);
        int r0 = w * 16 + g;
        if (tg == 0) { pl[pi * 128 + r0] = l0; pl[pi * 128 + r0 + 8] = l1; }
#pragma unroll
        for (int ni = 0; ni < 8; ni++) {
            int col = ni * 8 + tg * 2;
            *(float2*)(pOb + r0 * 64 + col) = make_float2(oc[ni][0], oc[ni][1]);
            *(float2*)(pOb + (r0 + 8) * 64 + col) = make_float2(oc[ni][2], oc[ni][3]);
        }
    }
}

// ---------------------------------------------------------------------------
// Split-K reduce: sum 8 chunks, normalize, round, write to g_attn.
// ---------------------------------------------------------------------------
__global__ void attn_reduce(const float* __restrict__ pO, const float* __restrict__ pl,
                            float* __restrict__ out)
{
    int idx = blockIdx.x * 256 + threadIdx.x;   // 2^18 total
    int d2 = idx & 31;
    int row = (idx >> 5) & 127;
    int qt = (idx >> 12) & 3;
    int bh = idx >> 14;
    int base = (bh * 4 + qt) * 8;

    float l = 0.f;
#pragma unroll
    for (int c = 0; c < 8; c++) l += pl[(base + c) * 128 + row];
    float ox = 0.f, oy = 0.f;
#pragma unroll
    for (int c = 0; c < 8; c++) {
        float2 v = *(const float2*)(pO + (size_t)(base + c) * (128 * 64) + row * 64 + d2 * 2);
        ox += v.x; oy += v.y;
    }
    float inv = 1.f / l;
    int b = bh >> 3, h = bh & 7;
    int q = qt * 128 + row;
    *(float2*)(out + (size_t)(b * SS + q) * HH + h * HD + d2 * 2) =
        make_float2(rtf(ox * inv), rtf(oy * inv));
}

// ---------------------------------------------------------------------------
extern "C" void kernel_launch(void* const* d_in, const int* in_sizes, int n_in,
                              void* d_out, int out_size)
{
    (void)in_sizes; (void)n_in; (void)out_size;
    const float* x    = (const float*)d_in[0];
    const float* wqkv = (const float*)d_in[1];
    const float* wout = (const float*)d_in[2];
    const float* bout = (const float*)d_in[3];
    float* out = (float*)d_out;

    void *xr, *wqkvr, *woutr, *qkvp, *vTp, *attnp, *pOp, *plp;
    cudaGetSymbolAddress(&xr, g_xr);
    cudaGetSymbolAddress(&wqkvr, g_wqkvr);
    cudaGetSymbolAddress(&woutr, g_woutr);
    cudaGetSymbolAddress(&qkvp, g_qkv);
    cudaGetSymbolAddress(&vTp, g_vT);
    cudaGetSymbolAddress(&attnp, g_attn);
    cudaGetSymbolAddress(&pOp, g_pO);
    cudaGetSymbolAddress(&plp, g_pl);

    cudaFuncSetAttribute(gemm_db, cudaFuncAttributeMaxDynamicSharedMemorySize, GEMM_SMEM);
    cudaFuncSetAttribute(attn_tc, cudaFuncAttributeMaxDynamicSharedMemorySize, ATTN_SMEM);

    // pre-round inputs to tf32
    round_tf<<<MROWS * HH / 4 / 256, 256>>>(x, (float*)xr, MROWS * HH / 4);
    round_tf<<<QKV_COLS * HH / 4 / 256, 256>>>(wqkv, (float*)wqkvr, QKV_COLS * HH / 4);
    round_tf<<<HH * HH / 4 / 256, 256>>>(wout, (float*)woutr, HH * HH / 4);

    // 1) qkv projection (Q scaled+rounded, K rounded, V transposed+rounded)
    gemm_db<<<dim3(QKV_COLS / 128, MROWS / 128), 256, GEMM_SMEM>>>(
        (const float*)xr, (const float*)wqkvr, nullptr, (float*)qkvp,
        (float*)vTp, QKV_COLS, HH, 1);
    // 2) attention (truncated + split-K)
    attn_tc<<<dim3(60, BB * NH), 256, ATTN_SMEM>>>(
        (const float*)qkvp, (const float*)vTp, (float*)attnp,
        (float*)pOp, (float*)plp);
    attn_reduce<<<1024, 256>>>((const float*)pOp, (const float*)plp, (float*)attnp);
    // 3) output projection + bias
    gemm_db<<<dim3(HH / 128, MROWS / 128), 256, GEMM_SMEM>>>(
        (const float*)attnp, (const float*)woutr, bout, out, nullptr, HH, HH, 0);
}

// round 9
// speedup vs baseline: 3.3630x; 1.2496x over previous
#include <cuda_runtime.h>
#include <cstdint>

#define BB 2
#define SS 4096
#define HH 512
#define NH 8
#define HD 64
#define MROWS (BB * SS)
#define QKV_COLS (3 * HH)
#define LOG2D (-0.15200309344504997f)   // log2(0.9)
#define QSCALE 0.18033688011112042f     // 0.125 * log2(e)

// scratch (device globals; no allocation allowed)
__device__ float g_xr[MROWS * HH];
__device__ float g_wqkvr[QKV_COLS * HH];
__device__ float g_woutr[HH * HH];
__device__ float g_qkv[MROWS * QKV_COLS];
__device__ float g_vT[BB * NH * HD * SS];
__device__ float g_attn[MROWS * HH];
__device__ float g_pO[256 * 128 * 64];        // split-K partial O (2 qtiles x 16 bh x 8 ck)
__device__ float g_pl[256 * 128];             // split-K partial l

__device__ __forceinline__ uint32_t f2tf(float x) {
    uint32_t r;
    asm("cvt.rna.tf32.f32 %0, %1;" : "=r"(r) : "f"(x));
    return r;
}
__device__ __forceinline__ float rtf(float x) { return __uint_as_float(f2tf(x)); }
__device__ __forceinline__ float ex2(float x) {
    float r;
    asm("ex2.approx.ftz.f32 %0, %1;" : "=f"(r) : "f"(x));
    return r;
}
__device__ __forceinline__ void mma8(float* d, const uint32_t* a, const uint32_t* b) {
    asm volatile(
        "mma.sync.aligned.m16n8k8.row.col.f32.tf32.tf32.f32 "
        "{%0,%1,%2,%3}, {%4,%5,%6,%7}, {%8,%9}, {%0,%1,%2,%3};\n"
        : "+f"(d[0]), "+f"(d[1]), "+f"(d[2]), "+f"(d[3])
        : "r"(a[0]), "r"(a[1]), "r"(a[2]), "r"(a[3]), "r"(b[0]), "r"(b[1]));
}
__device__ __forceinline__ void ldsm4(uint32_t* r, uint32_t saddr) {
    asm volatile("ldmatrix.sync.aligned.m8n8.x4.shared.b16 {%0,%1,%2,%3}, [%4];"
                 : "=r"(r[0]), "=r"(r[1]), "=r"(r[2]), "=r"(r[3]) : "r"(saddr));
}
__device__ __forceinline__ void cpa16(uint32_t dst, const void* src) {
    asm volatile("cp.async.cg.shared.global [%0], [%1], 16;" :: "r"(dst), "l"(src));
}
#define CP_COMMIT() asm volatile("cp.async.commit_group;" ::: "memory")
#define CP_WAIT0()  asm volatile("cp.async.wait_group 0;" ::: "memory")

#define AOFF(S) (((((mat & 1) << 3) + mr) * (S) + ((mat >> 1) << 2)) << 2)
#define BOFF(S) (((((mat >> 1) << 3) + mr) * (S) + ((mat & 1) << 2)) << 2)

// ---------------------------------------------------------------------------
__global__ void round_tf(const float* __restrict__ src, float* __restrict__ dst, int n4) {
    int i = blockIdx.x * 256 + threadIdx.x;
    if (i < n4) {
        float4 v = ((const float4*)src)[i];
        v.x = rtf(v.x); v.y = rtf(v.y); v.z = rtf(v.z); v.w = rtf(v.w);
        ((float4*)dst)[i] = v;
    }
}

// ---------------------------------------------------------------------------
// GEMM, inputs pre-rounded tf32. CTA 128x128, 8 warps, K chunks of 32,
// cp.async double-buffered. mode 0: fp32 +bias. mode 1: qkv epilogue.
// ---------------------------------------------------------------------------
#define GSTR 36
#define GEMM_SMEM (4 * 128 * GSTR * 4)

__global__ __launch_bounds__(256, 2) void gemm_db(
    const float* __restrict__ A, const float* __restrict__ W,
    const float* __restrict__ bias, float* __restrict__ C,
    float* __restrict__ vT, int Ndim, int Kdim, int mode)
{
    extern __shared__ uint32_t gsm[];
    const int tid = threadIdx.x;
    const int w = tid >> 5, lane = tid & 31;
    const int g = lane >> 2, tg = lane & 3;
    const int mat = lane >> 3, mr = lane & 7;
    const int wm = w & 3, wn = w >> 2;
    const int m0 = blockIdx.y * 128, n0 = blockIdx.x * 128;

    const uint32_t smu = (uint32_t)__cvta_generic_to_shared(gsm);
    const uint32_t sAu[2] = {smu, smu + 128 * GSTR * 4};
    const uint32_t sBu[2] = {smu + 2 * 128 * GSTR * 4, smu + 3 * 128 * GSTR * 4};
    const uint32_t a_off = AOFF(GSTR), b_off = BOFF(GSTR);

    float acc[2][8][4] = {};
    const int T = Kdim / 32;

#define GISSUE(t_, buf_) {                                                     \
        int kk_ = (t_) * 32;                                                   \
        _Pragma("unroll")                                                      \
        for (int it = 0; it < 4; it++) {                                       \
            int fi = it * 256 + tid;                                           \
            int r = fi >> 3, c = (fi & 7) << 2;                                \
            cpa16(sAu[buf_] + (r * GSTR + c) * 4,                              \
                  A + (size_t)(m0 + r) * Kdim + kk_ + c);                      \
            cpa16(sBu[buf_] + (r * GSTR + c) * 4,                              \
                  W + (size_t)(n0 + r) * Kdim + kk_ + c);                      \
        }                                                                      \
        CP_COMMIT();                                                           \
    }

    GISSUE(0, 0);
    for (int t = 0; t < T; t++) {
        const int cur = t & 1;
        CP_WAIT0();
        __syncthreads();
        if (t + 1 < T) GISSUE(t + 1, cur ^ 1);
#pragma unroll
        for (int ks = 0; ks < 4; ks++) {
            uint32_t afr[2][4];
            ldsm4(afr[0], sAu[cur] + (wm * 32) * (GSTR * 4) + a_off + ks * 32);
            ldsm4(afr[1], sAu[cur] + (wm * 32 + 16) * (GSTR * 4) + a_off + ks * 32);
#pragma unroll
            for (int p = 0; p < 4; p++) {
                uint32_t bfr[4];
                ldsm4(bfr, sBu[cur] + (wn * 64 + p * 16) * (GSTR * 4) + b_off + ks * 32);
                mma8(acc[0][2 * p + 0], afr[0], bfr);
                mma8(acc[0][2 * p + 1], afr[0], bfr + 2);
                mma8(acc[1][2 * p + 0], afr[1], bfr);
                mma8(acc[1][2 * p + 1], afr[1], bfr + 2);
            }
        }
    }

#pragma unroll
    for (int mi = 0; mi < 2; mi++)
#pragma unroll
        for (int ni = 0; ni < 8; ni++) {
            float* a = acc[mi][ni];
            int row = m0 + wm * 32 + mi * 16 + g;
            int col = n0 + wn * 64 + ni * 8 + tg * 2;
            if (mode == 0) {
                float b0 = bias ? bias[col] : 0.f;
                float b1 = bias ? bias[col + 1] : 0.f;
                *(float2*)(C + (size_t)row * Ndim + col) = make_float2(a[0] + b0, a[1] + b1);
                *(float2*)(C + (size_t)(row + 8) * Ndim + col) = make_float2(a[2] + b0, a[3] + b1);
            } else {
                int region = n0 >> 9;
                if (region < 2) {
                    float scl = (region == 0) ? QSCALE : 1.f;
                    *(float2*)(C + (size_t)row * Ndim + col) =
                        make_float2(rtf(a[0] * scl), rtf(a[1] * scl));
                    *(float2*)(C + (size_t)(row + 8) * Ndim + col) =
                        make_float2(rtf(a[2] * scl), rtf(a[3] * scl));
                } else {
                    int b = row >> 12, s = row & 4095;
                    int hv = (col - 1024) >> 6, d = (col - 1024) & 63;
                    float* vb = vT + (size_t)((b * NH + hv) * HD) * SS;
                    vb[(size_t)d * SS + s]           = rtf(a[0]);
                    vb[(size_t)(d + 1) * SS + s]     = rtf(a[1]);
                    vb[(size_t)d * SS + s + 8]       = rtf(a[2]);
                    vb[(size_t)(d + 1) * SS + s + 8] = rtf(a[3]);
                }
            }
        }
}

// ---------------------------------------------------------------------------
// TF32 flash attention, recency truncation v2 + additive split-K.
// Weight of element (q,k) ∝ 2^(s + min(k,q)*log2(0.9)): negligible whenever
// min(k,q) >= 256. Therefore:
//   rows q <  256 (qtiles 0,1):  exact, all 4096 keys, 8-way split-K
//   rows q >= 256 (qtiles 2..31): keys [0,256) only (8 key-tiles)
// grid (46, 16): bx<16 -> split: qt=bx>>3, ck=bx&7, 16 tiles over [512ck, 512ck+512)
//                bx>=16 -> qt=bx-14, ck=0, 8 tiles over [0,256)
// ---------------------------------------------------------------------------
#define QS 68
#define KSs 68
#define VS 36
#define PS 36
#define W_K0 (128 * QS)
#define W_V0 (W_K0 + 2 * 32 * KSs)
#define W_P  (W_V0 + 2 * 64 * VS)
#define ATTN_SMEM ((W_P + 128 * PS) * 4)   // 89088 B -> 2 CTAs/SM

__global__ __launch_bounds__(256, 2) void attn_tc(
    const float* __restrict__ qkv, const float* __restrict__ vT,
    float* __restrict__ out, float* __restrict__ pO, float* __restrict__ pl)
{
    extern __shared__ uint32_t sm[];

    const int tid = threadIdx.x;
    const int w = tid >> 5, lane = tid & 31;
    const int g = lane >> 2, tg = lane & 3;
    const int mat = lane >> 3, mr = lane & 7;
    const int bh = blockIdx.y;
    const int b = bh >> 3, h = bh & 7;

    int qt, ck, nT;
    if (blockIdx.x < 16) { qt = blockIdx.x >> 3; ck = blockIdx.x & 7; nT = 16; }
    else                 { qt = blockIdx.x - 14; ck = 0; nT = 8; }
    const bool split = (blockIdx.x < 16);
    const int q0 = qt * 128;
    const int k0 = ck * 512;

    const float* qbase = qkv + (size_t)b * SS * QKV_COLS + h * HD;
    const float* kbase = qbase + HH;
    const float* vtb = vT + (size_t)bh * HD * SS;

    const uint32_t smu = (uint32_t)__cvta_generic_to_shared(sm);
    const uint32_t sQu = smu;
    const uint32_t sKu[2] = {smu + W_K0 * 4, smu + (W_K0 + 32 * KSs) * 4};
    const uint32_t sVu[2] = {smu + W_V0 * 4, smu + (W_V0 + 64 * VS) * 4};
    const uint32_t sPu = smu + W_P * 4;

    const uint32_t qa = sQu + w * (16 * QS * 4) + AOFF(QS);
    const uint32_t pa = sPu + w * (16 * PS * 4) + AOFF(PS);
    const uint32_t boffK = BOFF(KSs);
    const uint32_t boffV = BOFF(VS);

    // prologue: Q (128x64) + K/V tile 0
    {
#pragma unroll
        for (int it = 0; it < 8; it++) {
            int fi = it * 256 + tid;
            int r = fi >> 4, c = (fi & 15) << 2;
            cpa16(sQu + (r * QS + c) * 4, qbase + (size_t)(q0 + r) * QKV_COLS + c);
        }
#pragma unroll
        for (int it = 0; it < 2; it++) {
            int fi = it * 256 + tid;
            int r = fi >> 4, c = (fi & 15) << 2;
            cpa16(sKu[0] + (r * KSs + c) * 4, kbase + (size_t)(k0 + r) * QKV_COLS + c);
        }
#pragma unroll
        for (int it = 0; it < 2; it++) {
            int fi = it * 256 + tid;
            int r = fi >> 3, c = (fi & 7) << 2;
            cpa16(sVu[0] + (r * VS + c) * 4, vtb + (size_t)r * SS + k0 + c);
        }
        CP_COMMIT();
    }

    float colL[4][2];
#pragma unroll
    for (int ni = 0; ni < 4; ni++)
#pragma unroll
        for (int cc = 0; cc < 2; cc++)
            colL[ni][cc] = (float)(k0 + ni * 8 + tg * 2 + cc) * LOG2D;
    float qLf[2];
#pragma unroll
    for (int hi = 0; hi < 2; hi++)
        qLf[hi] = (float)(q0 + w * 16 + hi * 8 + g) * LOG2D;

    float oc[8][4] = {};
    float lacc[2] = {0.f, 0.f};

    for (int t = 0; t < nT; t++) {
        const int kt = k0 + t * 32;
        const int cur = t & 1;

        CP_WAIT0();
        __syncthreads();

        if (t + 1 < nT) {
            const int nxt = cur ^ 1;
#pragma unroll
            for (int it = 0; it < 2; it++) {
                int fi = it * 256 + tid;
                int r = fi >> 4, c = (fi & 15) << 2;
                cpa16(sKu[nxt] + (r * KSs + c) * 4,
                      kbase + (size_t)(kt + 32 + r) * QKV_COLS + c);
            }
#pragma unroll
            for (int it = 0; it < 2; it++) {
                int fi = it * 256 + tid;
                int r = fi >> 3, c = (fi & 7) << 2;
                cpa16(sVu[nxt] + (r * VS + c) * 4,
                      vtb + (size_t)r * SS + kt + 32 + c);
            }
            CP_COMMIT();
        }

        // S = Q K^T
        float sc[4][4] = {};
#pragma unroll
        for (int ks = 0; ks < 8; ks++) {
            uint32_t afr[4];
            ldsm4(afr, qa + ks * 32);
#pragma unroll
            for (int p = 0; p < 2; p++) {
                uint32_t bfr[4];
                ldsm4(bfr, sKu[cur] + boffK + p * (16 * KSs * 4) + ks * 32);
                mma8(sc[2 * p + 0], afr, bfr);
                mma8(sc[2 * p + 1], afr, bfr + 2);
            }
        }

        // softmax: e = exp2(s + max(kL, qL))
#pragma unroll
        for (int hi = 0; hi < 2; hi++) {
            int prow = w * 16 + hi * 8 + g;
#pragma unroll
            for (int ni = 0; ni < 4; ni++) {
                uint32_t eb[2];
#pragma unroll
                for (int cc = 0; cc < 2; cc++) {
                    float e = ex2(sc[ni][hi * 2 + cc] + fmaxf(colL[ni][cc], qLf[hi]));
                    eb[cc] = f2tf(e);
                    lacc[hi] += __uint_as_float(eb[cc]);
                }
                uint32_t addr = sPu + (prow * PS + ni * 8 + tg * 2) * 4;
                asm volatile("st.shared.v2.u32 [%0], {%1,%2};"
                             :: "r"(addr), "r"(eb[0]), "r"(eb[1]));
            }
        }
#pragma unroll
        for (int ni = 0; ni < 4; ni++) {
            colL[ni][0] += 32.f * LOG2D;
            colL[ni][1] += 32.f * LOG2D;
        }
        __syncwarp();

        // O += P V
#pragma unroll
        for (int ks = 0; ks < 4; ks++) {
            uint32_t pfr[4];
            ldsm4(pfr, pa + ks * 32);
#pragma unroll
            for (int p = 0; p < 4; p++) {
                uint32_t vfr[4];
                ldsm4(vfr, sVu[cur] + boffV + p * (16 * VS * 4) + ks * 32);
                mma8(oc[2 * p + 0], pfr, vfr);
                mma8(oc[2 * p + 1], pfr, vfr + 2);
            }
        }
    }

    float l0 = lacc[0], l1 = lacc[1];
    l0 += __shfl_xor_sync(0xffffffffu, l0, 1);
    l0 += __shfl_xor_sync(0xffffffffu, l0, 2);
    l1 += __shfl_xor_sync(0xffffffffu, l1, 1);
    l1 += __shfl_xor_sync(0xffffffffu, l1, 2);

    if (!split) {
        float inv0 = 1.0f / l0, inv1 = 1.0f / l1;
#pragma unroll
        for (int ni = 0; ni < 8; ni++) {
            int row = q0 + w * 16 + g;
            int col = h * HD + ni * 8 + tg * 2;
            *(float2*)(out + (size_t)(b * SS + row) * HH + col) =
                make_float2(rtf(oc[ni][0] * inv0), rtf(oc[ni][1] * inv0));
            *(float2*)(out + (size_t)(b * SS + row + 8) * HH + col) =
                make_float2(rtf(oc[ni][2] * inv1), rtf(oc[ni][3] * inv1));
        }
    } else {
        int pi = (bh * 2 + qt) * 8 + ck;
        float* pOb = pO + (size_t)pi * (128 * 64);
        int r0 = w * 16 + g;
        if (tg == 0) { pl[pi * 128 + r0] = l0; pl[pi * 128 + r0 + 8] = l1; }
#pragma unroll
        for (int ni = 0; ni < 8; ni++) {
            int col = ni * 8 + tg * 2;
            *(float2*)(pOb + r0 * 64 + col) = make_float2(oc[ni][0], oc[ni][1]);
            *(float2*)(pOb + (r0 + 8) * 64 + col) = make_float2(oc[ni][2], oc[ni][3]);
        }
    }
}

// ---------------------------------------------------------------------------
// Split-K reduce: sum 8 chunks, normalize, round, write (2 qtiles per head).
// ---------------------------------------------------------------------------
__global__ void attn_reduce(const float* __restrict__ pO, const float* __restrict__ pl,
                            float* __restrict__ out)
{
    int idx = blockIdx.x * 256 + threadIdx.x;   // 131072 total
    int d2 = idx & 31;
    int row = (idx >> 5) & 127;
    int qt = (idx >> 12) & 1;
    int bh = idx >> 13;
    int base = (bh * 2 + qt) * 8;

    float l = 0.f;
#pragma unroll
    for (int c = 0; c < 8; c++) l += pl[(base + c) * 128 + row];
    float ox = 0.f, oy = 0.f;
#pragma unroll
    for (int c = 0; c < 8; c++) {
        float2 v = *(const float2*)(pO + (size_t)(base + c) * (128 * 64) + row * 64 + d2 * 2);
        ox += v.x; oy += v.y;
    }
    float inv = 1.f / l;
    int b = bh >> 3, h = bh & 7;
    int q = qt * 128 + row;
    *(float2*)(out + (size_t)(b * SS + q) * HH + h * HD + d2 * 2) =
        make_float2(rtf(ox * inv), rtf(oy * inv));
}

// ---------------------------------------------------------------------------
extern "C" void kernel_launch(void* const* d_in, const int* in_sizes, int n_in,
                              void* d_out, int out_size)
{
    (void)in_sizes; (void)n_in; (void)out_size;
    const float* x    = (const float*)d_in[0];
    const float* wqkv = (const float*)d_in[1];
    const float* wout = (const float*)d_in[2];
    const float* bout = (const float*)d_in[3];
    float* out = (float*)d_out;

    void *xr, *wqkvr, *woutr, *qkvp, *vTp, *attnp, *pOp, *plp;
    cudaGetSymbolAddress(&xr, g_xr);
    cudaGetSymbolAddress(&wqkvr, g_wqkvr);
    cudaGetSymbolAddress(&woutr, g_woutr);
    cudaGetSymbolAddress(&qkvp, g_qkv);
    cudaGetSymbolAddress(&vTp, g_vT);
    cudaGetSymbolAddress(&attnp, g_attn);
    cudaGetSymbolAddress(&pOp, g_pO);
    cudaGetSymbolAddress(&plp, g_pl);

    cudaFuncSetAttribute(gemm_db, cudaFuncAttributeMaxDynamicSharedMemorySize, GEMM_SMEM);
    cudaFuncSetAttribute(attn_tc, cudaFuncAttributeMaxDynamicSharedMemorySize, ATTN_SMEM);

    round_tf<<<MROWS * HH / 4 / 256, 256>>>(x, (float*)xr, MROWS * HH / 4);
    round_tf<<<QKV_COLS * HH / 4 / 256, 256>>>(wqkv, (float*)wqkvr, QKV_COLS * HH / 4);
    round_tf<<<HH * HH / 4 / 256, 256>>>(wout, (float*)woutr, HH * HH / 4);

    gemm_db<<<dim3(QKV_COLS / 128, MROWS / 128), 256, GEMM_SMEM>>>(
        (const float*)xr, (const float*)wqkvr, nullptr, (float*)qkvp,
        (float*)vTp, QKV_COLS, HH, 1);
    attn_tc<<<dim3(46, BB * NH), 256, ATTN_SMEM>>>(
        (const float*)qkvp, (const float*)vTp, (float*)attnp,
        (float*)pOp, (float*)plp);
    attn_reduce<<<512, 256>>>((const float*)pOp, (const float*)plp, (float*)attnp);
    gemm_db<<<dim3(HH / 128, MROWS / 128), 256, GEMM_SMEM>>>(
        (const float*)attnp, (const float*)woutr, bout, out, nullptr, HH, HH, 0);
}